// round 15
// baseline (speedup 1.0000x reference)
#include <cuda_runtime.h>
#include <cuda_fp16.h>
#include <math.h>
#include <stdint.h>

#define PP   25
#define QQ   2000
#define CC   640
#define SS   25
#define TILE 16000

#define MPAD 640
#define NKC  40
#define CHUNK_BYTES (MPAD * 32)   // 20480
#define AT1S  632

#define OFT_TE  400000
#define OFT_AM  32400000
#define OFT_CLS 32450000

__device__ __align__(16) unsigned char g_Ah[NKC * CHUNK_BYTES];
__device__ __align__(16) float g_att1[QQ * AT1S];
__device__ float g_part[200 * SS];

// ---------------- smem layout (cam_main, 1 q per CTA, ~104 KB) ----------------
#define OB_RING  0         // 3 x 20480 = 61440 ; G fp16 (32512) overlays [0,32512) after GEMM
#define OB_STAGE 32512     // output fq staging 64000 -> ends 96512 (over dead ring tail + B)
#define OB_B     64000     // 32400 -> 96400 (dead after GEMM)
#define OB_AT1   96512     // 632 x 4
#define OB_ATT   99040     // 625 x 4
#define OB_KN    101540    // 8 x 112 x 4 = 3584
#define OB_W1F   105124    // 125 f
#define OB_W2    105624    // 125 f
#define OB_B1F   106124    // 5 f
#define OB_B2S   106144    // 25 f
#define OB_NINV  106244    // 25 f
#define OB_TS    106344    // 25 f
#define OB_MBAR  106448    // 4 mbarriers
#define SMEM_BYTES 106496

#define AT1I (OB_AT1/4)
#define ATI  (OB_ATT/4)
#define KNI  (OB_KN/4)

__device__ __forceinline__ float warp_sum(float v) {
    #pragma unroll
    for (int o = 16; o; o >>= 1) v += __shfl_xor_sync(0xffffffffu, v, o);
    return v;
}
__device__ __forceinline__ void mbar_init(uint32_t mbar, uint32_t cnt) {
    asm volatile("mbarrier.init.shared.b64 [%0], %1;" :: "r"(mbar), "r"(cnt) : "memory");
}
__device__ __forceinline__ void mbar_expect_tx(uint32_t mbar, uint32_t bytes) {
    asm volatile("mbarrier.arrive.expect_tx.shared.b64 _, [%0], %1;"
                 :: "r"(mbar), "r"(bytes) : "memory");
}
__device__ __forceinline__ void mbar_wait(uint32_t mbar, uint32_t parity) {
    asm volatile(
        "{\n\t.reg .pred P;\n\t"
        "W_%=:\n\t"
        "mbarrier.try_wait.parity.acquire.cta.shared::cta.b64 P, [%0], %1, 0x989680;\n\t"
        "@P bra D_%=;\n\t"
        "bra.uni W_%=;\n\t"
        "D_%=:\n\t}"
        :: "r"(mbar), "r"(parity) : "memory");
}
__device__ __forceinline__ void bulk_ld(uint32_t dst, const void* src, uint32_t bytes,
                                        uint32_t mbar) {
    asm volatile("cp.async.bulk.shared::cluster.global.mbarrier::complete_tx::bytes "
                 "[%0], [%1], %2, [%3];"
                 :: "r"(dst), "l"(src), "r"(bytes), "r"(mbar) : "memory");
}
__device__ __forceinline__ void bulk_st(void* gdst, uint32_t ssrc, uint32_t bytes) {
    asm volatile("cp.async.bulk.global.shared::cta.bulk_group [%0], [%1], %2;"
                 :: "l"(gdst), "r"(ssrc), "r"(bytes) : "memory");
}
#define BULK_COMMIT() asm volatile("cp.async.bulk.commit_group;" ::: "memory")
#define BULK_WAIT0()  asm volatile("cp.async.bulk.wait_group 0;" ::: "memory")
#define FENCE_ASYNC() asm volatile("fence.proxy.async.shared::cta;" ::: "memory")

__device__ __forceinline__ void ldsm_x4(uint32_t& r0, uint32_t& r1, uint32_t& r2, uint32_t& r3,
                                        uint32_t addr) {
    asm volatile("ldmatrix.sync.aligned.m8n8.x4.shared.b16 {%0,%1,%2,%3}, [%4];"
                 : "=r"(r0), "=r"(r1), "=r"(r2), "=r"(r3) : "r"(addr));
}
__device__ __forceinline__ void mma16816h(uint32_t& d0, uint32_t& d1,
                                          uint32_t a0, uint32_t a1, uint32_t a2, uint32_t a3,
                                          uint32_t b0, uint32_t b1) {
    asm volatile("mma.sync.aligned.m16n8k16.row.col.f16.f16.f16.f16 "
                 "{%0,%1}, {%2,%3,%4,%5}, {%6,%7}, {%0,%1};"
                 : "+r"(d0), "+r"(d1)
                 : "r"(a0), "r"(a1), "r"(a2), "r"(a3), "r"(b0), "r"(b1));
}

// ---------------- K1: build swizzled fp16 A image ----------------
__global__ void __launch_bounds__(256) cam_prep_A(const float* __restrict__ ftrain) {
    extern __shared__ float sm[];
    float* xs    = sm;
    float* inv_s = sm + 16000;
    unsigned char* buf = (unsigned char*)sm + 64128;
    int p = blockIdx.x, tid = threadIdx.x, lane = tid & 31, w = tid >> 5;
    const float4* fp4 = (const float4*)(ftrain + p * TILE);
    float4* xs4 = (float4*)xs;
    for (int i = tid; i < 4000; i += 256) xs4[i] = fp4[i];
    __syncthreads();
    for (int s = w; s < SS; s += 8) {
        float acc = 0.f;
        #pragma unroll
        for (int k = 0; k < 20; k++) { float v = xs[(lane + 32 * k) * SS + s]; acc += v * v; }
        acc = warp_sum(acc);
        if (lane == 0) inv_s[s] = 1.f / fmaxf(sqrtf(acc), 1e-12f);
    }
    __syncthreads();
    for (int idx = tid; idx < TILE; idx += 256) {
        int c = idx / SS, s = idx - c * SS;
        __half v = __float2half_rn(xs[idx] * inv_s[s]);
        int m = p * SS + s;
        int kc = c >> 4, k = c & 15;
        uint32_t off = (uint32_t)((((k >> 3) ^ ((m >> 2) & 1)) << 4) + ((k & 7) << 1));
        *(__half*)(buf + kc * 800 + s * 32 + off) = v;
    }
    __syncthreads();
    for (int i = tid; i < 2000; i += 256) {
        int kc = i / 50, j = i - kc * 50;
        *(float4*)(g_Ah + (size_t)(kc * MPAD + p * SS) * 32 + j * 16) =
            *(const float4*)(buf + kc * 800 + j * 16);
    }
}

// ---------------- K2: main kernel, 1 q per CTA, 256 thr, 2 CTAs/SM ----------------
__global__ void __launch_bounds__(256, 2) cam_main(
    const float* __restrict__ ftest,
    const float* __restrict__ conv1_w, const float* __restrict__ conv1_b,
    const float* __restrict__ bn_gamma, const float* __restrict__ bn_beta,
    const float* __restrict__ bn_mean, const float* __restrict__ bn_var,
    const float* __restrict__ conv2_w, const float* __restrict__ conv2_b,
    float* __restrict__ out)
{
    extern __shared__ char smraw[];
    float* smf = (float*)smraw;
    const int tid = threadIdx.x, lane = tid & 31, w = tid >> 5;
    const int q = blockIdx.x;
    const uint32_t smb = (uint32_t)__cvta_generic_to_shared(smraw);
    const uint32_t MB = smb + OB_MBAR;

    if (tid == 0) {
        #pragma unroll
        for (int b = 0; b < 4; b++) mbar_init(MB + b * 8, 1);
    }
    for (int i = tid; i < 125; i += 256) {
        int cc = i / 25;
        smf[OB_W1F/4 + i] = conv1_w[i] * bn_gamma[cc] * rsqrtf(bn_var[cc] + 1e-5f);
        smf[OB_W2/4 + i]  = conv2_w[i];
    }
    if (tid < 5) {
        float scv = bn_gamma[tid] * rsqrtf(bn_var[tid] + 1e-5f);
        smf[OB_B1F/4 + tid] = (conv1_b[tid] - bn_mean[tid]) * scv + bn_beta[tid];
    }
    if (tid < 25) smf[OB_B2S/4 + tid] = conv2_b[tid];
    __syncthreads();   // mbarrier init visible

    // start A stream immediately (independent of setup): prefetch chunks 0,1
    if (tid == 0) {
        #pragma unroll
        for (int pc = 0; pc < 2; pc++) {
            mbar_expect_tx(MB + pc * 8, CHUNK_BYTES);
            bulk_ld(smb + OB_RING + pc * CHUNK_BYTES, g_Ah + (size_t)pc * CHUNK_BYTES,
                    CHUNK_BYTES, MB + pc * 8);
        }
    }

    // ---- setup from global (fq is 64 KB, L1-resident after first pass) ----
    const float* fq = ftest + (size_t)q * TILE;
    for (int s = w; s < SS; s += 8) {
        float acc = 0.f;
        #pragma unroll
        for (int k = 0; k < 20; k++) { float v = __ldg(fq + (lane + 32 * k) * SS + s); acc += v * v; }
        acc = warp_sum(acc);
        if (lane == 0) smf[OB_NINV/4 + s] = 1.f / fmaxf(sqrtf(acc), 1e-12f);
    }
    __syncthreads();
    for (int i = tid; i < 8000; i += 256) {
        int s = i / 320, c2 = i - s * 320;
        float iv = smf[OB_NINV/4 + s];
        __half2 v = __floats2half2_rn(__ldg(fq + (2 * c2) * SS + s) * iv,
                                      __ldg(fq + (2 * c2 + 1) * SS + s) * iv);
        *(__half2*)(smraw + OB_B + (s * 648 + 2 * c2) * 2) = v;
    }

    // ---- GEMM: each warp 5 m-tiles {w, w+8, ..., w+32} x 4 n-tiles ----
    uint32_t hacc[5][4][2];
    #pragma unroll
    for (int t = 0; t < 5; t++)
        #pragma unroll
        for (int n = 0; n < 4; n++) { hacc[t][n][0] = 0u; hacc[t][n][1] = 0u; }

    const int nrow = lane >> 2;
    const int kq   = lane & 3;

    for (int i = 0; i < NKC; i++) {
        __syncthreads();   // (i=0: B ready; i>0: reads of slot (i+2)%3 from iter i-1 done)
        if (tid == 0 && i + 2 < NKC) {
            int b = (i + 2) % 3;
            mbar_expect_tx(MB + b * 8, CHUNK_BYTES);
            bulk_ld(smb + OB_RING + b * CHUNK_BYTES, g_Ah + (size_t)(i + 2) * CHUNK_BYTES,
                    CHUNK_BYTES, MB + b * 8);
        }
        mbar_wait(MB + (i % 3) * 8, (uint32_t)((i / 3) & 1));
        const uint32_t abase = smb + OB_RING + (i % 3) * CHUNK_BYTES;

        uint32_t bf[4][2];
        #pragma unroll
        for (int nt = 0; nt < 3; nt++) {
            int n = nt * 8 + nrow;
            uint32_t bidx = OB_B + (uint32_t)(n * 648 + i * 16 + kq * 2) * 2;
            bf[nt][0] = *(const uint32_t*)(smraw + bidx);
            bf[nt][1] = *(const uint32_t*)(smraw + bidx + 16);
        }
        if (nrow == 0) {
            uint32_t bidx = OB_B + (uint32_t)(24 * 648 + i * 16 + kq * 2) * 2;
            bf[3][0] = *(const uint32_t*)(smraw + bidx);
            bf[3][1] = *(const uint32_t*)(smraw + bidx + 16);
        } else {
            bf[3][0] = 0u; bf[3][1] = 0u;
        }

        #pragma unroll
        for (int j = 0; j < 5; j++) {
            int mt = w + 8 * j;
            int m = mt * 16 + (lane & 15);
            uint32_t addr = abase + m * 32 + ((((lane >> 4) ^ (m >> 2)) & 1) << 4);
            uint32_t a0, a1, a2, a3;
            ldsm_x4(a0, a1, a2, a3, addr);
            #pragma unroll
            for (int nt = 0; nt < 4; nt++)
                mma16816h(hacc[j][nt][0], hacc[j][nt][1],
                          a0, a1, a2, a3, bf[nt][0], bf[nt][1]);
        }
    }
    __syncthreads();   // ring + B dead

    // prefetch raw fq for output into STAGE region (over dead ring tail + B)
    if (tid == 0) {
        mbar_expect_tx(MB + 3 * 8, TILE * 4);
        bulk_ld(smb + OB_STAGE, fq, TILE * 4, MB + 3 * 8);
    }

    // ---- store G (fp16) into [0, 32512) ----
    {
        __half* gh = (__half*)(smraw + OB_RING);
        #pragma unroll
        for (int j = 0; j < 5; j++) {
            int mt = w + 8 * j;
            int r0 = mt * 16 + (lane >> 2);
            int r1 = r0 + 8;
            #pragma unroll
            for (int nt = 0; nt < 4; nt++) {
                int c = nt * 8 + (lane & 3) * 2;
                if (c + 1 < 25) {
                    if (r0 < 625) *(uint32_t*)(gh + r0 * 26 + c) = hacc[j][nt][0];
                    if (r1 < 625) *(uint32_t*)(gh + r1 * 26 + c) = hacc[j][nt][1];
                } else if (c < 25) {
                    __half2 v0 = *reinterpret_cast<__half2*>(&hacc[j][nt][0]);
                    __half2 v1 = *reinterpret_cast<__half2*>(&hacc[j][nt][1]);
                    if (r0 < 625) gh[r0 * 26 + c] = __low2half(v0);
                    if (r1 < 625) gh[r1 * 26 + c] = __low2half(v1);
                }
            }
        }
    }
    __syncthreads();

    // ---- per-p epilogue: 25 tasks over 8 warps ----
    {
        const __half* gh = (const __half*)(smraw + OB_RING);
        for (int p = w; p < PP; p += 8) {
            float* kn = smf + KNI + w * 112;
            if (lane < 25) {
                float a1 = 0.f, a2 = 0.f;
                int rowb = (p * 25 + lane) * 26;
                int colb = p * 25 * 26 + lane;
                #pragma unroll
                for (int j = 0; j < 25; j++) {
                    a1 += __half2float(gh[rowb + j]);
                    a2 += __half2float(gh[colb + j * 26]);
                }
                kn[lane]      = a1 * (1.f / 25.f);
                kn[25 + lane] = a2 * (1.f / 25.f);
            }
            __syncwarp();
            if (lane < 5) {
                float a = smf[OB_B1F/4 + lane];
                #pragma unroll
                for (int j = 0; j < 25; j++) a += kn[j] * smf[OB_W1F/4 + lane * 25 + j];
                kn[50 + lane] = fmaxf(a, 0.f);
            } else if (lane >= 8 && lane < 13) {
                int ii = lane - 8;
                float a = smf[OB_B1F/4 + ii];
                #pragma unroll
                for (int j = 0; j < 25; j++) a += kn[25 + j] * smf[OB_W1F/4 + ii * 25 + j];
                kn[55 + ii] = fmaxf(a, 0.f);
            }
            __syncwarp();
            if (lane < 25) {
                float a1 = smf[OB_B2S/4 + lane], a2 = a1;
                #pragma unroll
                for (int ii = 0; ii < 5; ii++) {
                    float wv = smf[OB_W2/4 + lane * 5 + ii];
                    a1 += kn[50 + ii] * wv;
                    a2 += kn[55 + ii] * wv;
                }
                kn[60 + lane] = fmaxf(a1, 0.f);
                kn[85 + lane] = fmaxf(a2, 0.f);
            }
            __syncwarp();
            if (lane < 25) {
                float att1 = 0.f, attt = 0.f;
                int colb = p * 25 * 26 + lane;
                int rowb = (p * 25 + lane) * 26;
                #pragma unroll
                for (int j = 0; j < 25; j++) {
                    att1 += kn[60 + j] * __half2float(gh[colb + j * 26]);
                    attt += __half2float(gh[rowb + j]) * kn[85 + j];
                }
                smf[AT1I + p * 25 + lane] = att1;
                smf[ATI + p * 25 + lane]  = attt;
            }
        }
    }
    __syncthreads();

    // ---- softmaxes: warp 0 am, warp 1 cls ----
    if (w == 0) {
        float val = 0.f;
        if (lane < 25) {
            #pragma unroll
            for (int j = 0; j < 25; j++) val += smf[ATI + j * 25 + lane];
            val *= (1.f / 25.f);
        }
        float m = (lane < 25) ? val : -1e30f;
        #pragma unroll
        for (int o = 16; o; o >>= 1) m = fmaxf(m, __shfl_xor_sync(0xffffffffu, m, o));
        float e = (lane < 25) ? expf(val - m) : 0.f;
        float ssum = e;
        #pragma unroll
        for (int o = 16; o; o >>= 1) ssum += __shfl_xor_sync(0xffffffffu, ssum, o);
        float a = e / ssum;
        if (lane < 25) {
            out[OFT_AM + q * SS + lane] = a;
            smf[OB_TS/4 + lane] = a + 1.f;
        }
    } else if (w == 1) {
        float rs = 0.f;
        if (lane < 25) {
            #pragma unroll
            for (int j = 0; j < 25; j++) rs += smf[ATI + lane * 25 + j];
        }
        int g = (lane < 5) ? lane : 4;
        float cg = 0.f;
        #pragma unroll
        for (int i = 0; i < 5; i++) cg += __shfl_sync(0xffffffffu, rs, g * 5 + i);
        cg *= (1.f / 125.f);
        float m = (lane < 5) ? cg : -1e30f;
        #pragma unroll
        for (int o = 4; o; o >>= 1) m = fmaxf(m, __shfl_xor_sync(0xffffffffu, m, o));
        float e = (lane < 5) ? expf(cg - m) : 0.f;
        float ssum = e;
        #pragma unroll
        for (int o = 4; o; o >>= 1) ssum += __shfl_xor_sync(0xffffffffu, ssum, o);
        if (lane < 5) out[OFT_CLS + q * 5 + lane] = e / ssum;
    }
    __syncthreads();   // TS ready

    // ---- output: scale staged fq, bulk-store out + att1 ----
    {
        mbar_wait(MB + 3 * 8, 0);
        float4* st4 = (float4*)(smraw + OB_STAGE);
        for (int i = tid; i < 4000; i += 256) {
            float4 b = st4[i];
            int s = (i * 4) % 25;
            b.x *= smf[OB_TS/4 + s]; s = (s == 24) ? 0 : s + 1;
            b.y *= smf[OB_TS/4 + s]; s = (s == 24) ? 0 : s + 1;
            b.z *= smf[OB_TS/4 + s]; s = (s == 24) ? 0 : s + 1;
            b.w *= smf[OB_TS/4 + s];
            st4[i] = b;
        }
        __syncthreads();
        if (tid == 0) {
            FENCE_ASYNC();
            bulk_st(out + OFT_TE + (size_t)q * TILE, smb + OB_STAGE, TILE * 4);
            bulk_st(g_att1 + (size_t)q * AT1S, smb + OB_AT1, AT1S * 4);
            BULK_COMMIT();
            BULK_WAIT0();
        }
    }
    __syncthreads();   // keep smem alive until bulk stores complete
}

// ---------------- K3a: partial reduce of att1 over q slices ----------------
__global__ void __launch_bounds__(128) cam_final1() {
    __shared__ float red[125];
    int p = blockIdx.x >> 3, sl = blockIdx.x & 7;
    int tid = threadIdx.x;
    if (tid < 125) {
        int s = tid % 25, grp = tid / 25;
        const float* base = g_att1 + p * 25 + s;
        float acc = 0.f;
        for (int qq = sl * 250 + grp; qq < (sl + 1) * 250; qq += 5)
            acc += base[(size_t)qq * AT1S];
        red[tid] = acc;
    }
    __syncthreads();
    if (tid < 25) {
        float v = red[tid] + red[25 + tid] + red[50 + tid] + red[75 + tid] + red[100 + tid];
        g_part[blockIdx.x * 25 + tid] = v;
    }
}

// ---------------- K3b: combine, softmax, ftrain_out ----------------
__global__ void __launch_bounds__(256) cam_final2(const float* __restrict__ ftrain,
                                                  float* __restrict__ out) {
    __shared__ float att_s[SS];
    int p = blockIdx.x, tid = threadIdx.x, lane = tid & 31, w = tid >> 5;
    if (w == 0) {
        float val = 0.f;
        if (lane < 25) {
            #pragma unroll
            for (int k = 0; k < 8; k++) val += g_part[(p * 8 + k) * 25 + lane];
            val *= (1.f / (float)QQ);
        }
        float m = (lane < 25) ? val : -1e30f;
        #pragma unroll
        for (int o = 16; o; o >>= 1) m = fmaxf(m, __shfl_xor_sync(0xffffffffu, m, o));
        float e = (lane < 25) ? expf(val - m) : 0.f;
        float ssum = e;
        #pragma unroll
        for (int o = 16; o; o >>= 1) ssum += __shfl_xor_sync(0xffffffffu, ssum, o);
        if (lane < 25) att_s[lane] = e / ssum + 1.f;
    }
    __syncthreads();
    const float4* fp4 = (const float4*)(ftrain + p * TILE);
    float4* outp = (float4*)(out + (size_t)p * TILE);
    for (int i = tid; i < 4000; i += 256) {
        float4 b = fp4[i];
        int s = (i * 4) % 25;
        float4 o;
        o.x = b.x * att_s[s]; s = (s == 24) ? 0 : s + 1;
        o.y = b.y * att_s[s]; s = (s == 24) ? 0 : s + 1;
        o.z = b.z * att_s[s]; s = (s == 24) ? 0 : s + 1;
        o.w = b.w * att_s[s];
        outp[i] = o;
    }
}

// ---------------- launch ----------------
extern "C" void kernel_launch(void* const* d_in, const int* in_sizes, int n_in,
                              void* d_out, int out_size) {
    const float* ftrain  = (const float*)d_in[0];
    const float* ftest   = (const float*)d_in[1];
    const float* conv1_w = (const float*)d_in[6];
    const float* conv1_b = (const float*)d_in[7];
    const float* bn_gamma= (const float*)d_in[8];
    const float* bn_beta = (const float*)d_in[9];
    const float* bn_mean = (const float*)d_in[10];
    const float* bn_var  = (const float*)d_in[11];
    const float* conv2_w = (const float*)d_in[12];
    const float* conv2_b = (const float*)d_in[13];
    float* out = (float*)d_out;

    const int prepA_smem = 64128 + 32000;
    cudaFuncSetAttribute(cam_prep_A, cudaFuncAttributeMaxDynamicSharedMemorySize, prepA_smem);
    cudaFuncSetAttribute(cam_main,   cudaFuncAttributeMaxDynamicSharedMemorySize, SMEM_BYTES);

    cam_prep_A<<<PP, 256, prepA_smem>>>(ftrain);
    cam_main<<<QQ, 256, SMEM_BYTES>>>(ftest, conv1_w, conv1_b, bn_gamma, bn_beta,
                                      bn_mean, bn_var, conv2_w, conv2_b, out);
    cam_final1<<<200, 128>>>();
    cam_final2<<<PP, 256>>>(ftrain, out);
}